// round 5
// baseline (speedup 1.0000x reference)
#include <cuda_runtime.h>
#include <cstdint>
#include <math.h>

#define TPB 256
#define CH 30
#define MAXG 4096

__device__ float g_partials[MAXG];
__device__ int   g_count;            // zero-init; reset by last block each launch

__global__ void __launch_bounds__(TPB)
yolo_direct(const float* __restrict__ predicts,
            const float* __restrict__ targets,
            int n_cells, float* __restrict__ out)
{
    __shared__ float red[TPB];
    __shared__ bool  is_last;

    const int tid  = threadIdx.x;
    const int cell = blockIdx.x * TPB + tid;

    float loss = 0.0f;

    if (cell < n_cells) {
        const long long base = (long long)cell * CH;
        const float tconf = __ldg(targets + base + 4);

        if (!(tconf > 0.0f)) {
            // no-object: only conf channels of the two predictors
            float c1 = __ldg(predicts + base + 4);
            float c2 = __ldg(predicts + base + 9);
            loss = 0.5f * (c1 * c1 + c2 * c2);
        } else {
            // object cell: load both full 30-float vectors (8B-aligned float2s)
            const float2* p2 = reinterpret_cast<const float2*>(predicts + base);
            const float2* t2 = reinterpret_cast<const float2*>(targets + base);
            float p[CH], t[CH];
#pragma unroll
            for (int j = 0; j < 15; j++) {
                float2 a = __ldg(p2 + j);
                float2 b = __ldg(t2 + j);
                p[2 * j] = a.x; p[2 * j + 1] = a.y;
                t[2 * j] = b.x; t[2 * j + 1] = b.y;
            }

            const int within = cell % 49;
            const int yi = within / 7;
            const float gy = (float)yi;
            const float gx = (float)(within - yi * 7);
            const float ratio = 1.0f / 7.0f;

            // target abs box
            float tcx = (t[0] + gx) * ratio;
            float tcy = (t[1] + gy) * ratio;
            float tw = t[2], th = t[3];
            float tx1 = tcx - tw * 0.5f, ty1 = tcy - th * 0.5f;
            float tx2 = tcx + tw * 0.5f, ty2 = tcy + th * 0.5f;
            float areaT = (tx2 - tx1) * (ty2 - ty1);

            auto iou_with = [&](const float* b) -> float {
                float bcx = (b[0] + gx) * ratio;
                float bcy = (b[1] + gy) * ratio;
                float bw = b[2], bh = b[3];
                float x1 = bcx - bw * 0.5f, y1 = bcy - bh * 0.5f;
                float x2 = bcx + bw * 0.5f, y2 = bcy + bh * 0.5f;
                float iw = fmaxf(fminf(x2, tx2) - fmaxf(x1, tx1), 0.0f);
                float ih = fmaxf(fminf(y2, ty2) - fmaxf(y1, ty1), 0.0f);
                float inter = iw * ih;
                float area = (x2 - x1) * (y2 - y1);
                return inter / (area + areaT - inter);
            };

            float iou1 = iou_with(p);
            float iou2 = iou_with(p + 5);
            bool resp = iou1 > iou2;
            const float* pc = resp ? p : (p + 5);
            float iouS = resp ? iou1 : iou2;

            float dx = pc[0] - t[0];
            float dy = pc[1] - t[1];
            float sw = sqrtf(fmaxf(pc[2], 1e-6f)) - sqrtf(fmaxf(t[2], 1e-6f));
            float sh = sqrtf(fmaxf(pc[3], 1e-6f)) - sqrtf(fmaxf(t[3], 1e-6f));
            float coord = 5.0f * (dx * dx + dy * dy + sw * sw + sh * sh);

            float dc = pc[4] - iouS;
            float conf = dc * dc;

            float cls = 0.0f;
#pragma unroll
            for (int k = 10; k < 30; k++) {
                float d = p[k] - t[k];
                cls += d * d;
            }
            loss = coord + conf + cls;
        }
    }

    // deterministic block tree reduction
    red[tid] = loss;
    __syncthreads();
#pragma unroll
    for (int s = TPB / 2; s >= 32; s >>= 1) {
        if (tid < s) red[tid] += red[tid + s];
        __syncthreads();
    }
    if (tid < 32) {
        float v = red[tid];
#pragma unroll
        for (int off = 16; off > 0; off >>= 1)
            v += __shfl_down_sync(0xFFFFFFFFu, v, off);
        if (tid == 0) {
            g_partials[blockIdx.x] = v;
            __threadfence();
            int old = atomicAdd(&g_count, 1);
            is_last = (old == gridDim.x - 1);
        }
    }
    __syncthreads();

    // last block reduces all partials in a fixed order (deterministic)
    if (is_last) {
        const int nb = gridDim.x;
        float v = 0.0f;
        for (int i = tid; i < nb; i += TPB)
            v += g_partials[i];
        red[tid] = v;
        __syncthreads();
#pragma unroll
        for (int s = TPB / 2; s >= 32; s >>= 1) {
            if (tid < s) red[tid] += red[tid + s];
            __syncthreads();
        }
        if (tid < 32) {
            float w = red[tid];
#pragma unroll
            for (int off = 16; off > 0; off >>= 1)
                w += __shfl_down_sync(0xFFFFFFFFu, w, off);
            if (tid == 0) {
                out[0] = w;
                g_count = 0;            // reset for next graph replay
            }
        }
    }
}

extern "C" void kernel_launch(void* const* d_in, const int* in_sizes, int n_in,
                              void* d_out, int out_size)
{
    const float* predicts = (const float*)d_in[0];
    const float* targets  = (const float*)d_in[1];
    float* out = (float*)d_out;

    int n_cells = in_sizes[0] / CH;                 // 401408
    int blocks = (n_cells + TPB - 1) / TPB;         // 1568
    if (blocks > MAXG) blocks = MAXG;               // not hit for this shape

    yolo_direct<<<blocks, TPB>>>(predicts, targets, n_cells, out);
}